// round 7
// baseline (speedup 1.0000x reference)
#include <cuda_runtime.h>

#define NL 4
#define TPB 128

typedef unsigned long long u64;

// ---- packed 2x f32 (Blackwell f32x2 pipe) ----
struct p2 { u64 v; };

__device__ __forceinline__ p2 mk2(float lo, float hi) {
    p2 r; asm("mov.b64 %0, {%1,%2};" : "=l"(r.v) : "f"(lo), "f"(hi)); return r;
}
__device__ __forceinline__ void un2(p2 a, float& lo, float& hi) {
    asm("mov.b64 {%0,%1}, %2;" : "=f"(lo), "=f"(hi) : "l"(a.v));
}
__device__ __forceinline__ p2 fma2(p2 a, p2 b, p2 c) {
    p2 r; asm("fma.rn.f32x2 %0, %1, %2, %3;" : "=l"(r.v) : "l"(a.v), "l"(b.v), "l"(c.v)); return r;
}
__device__ __forceinline__ p2 mul2(p2 a, p2 b) {
    p2 r; asm("mul.rn.f32x2 %0, %1, %2;" : "=l"(r.v) : "l"(a.v), "l"(b.v)); return r;
}
__device__ __forceinline__ p2 neg2(p2 a) { p2 r; r.v = a.v ^ 0x8000000080000000ULL; return r; }

__device__ __forceinline__ float fast_tanh(float v) {
    float r; asm("tanh.approx.f32 %0, %1;" : "=f"(r) : "f"(v)); return r;
}

// ---- batch-invariant data: staged by setup kernel, then copied to __constant__ ----
// layout (float2, both lanes equal):
// [0:25)  params: 0-7 w1, 8-11 b1, 12-19 w2, 20-21 b2, 22-23 post_w, 24 post_b
// [25+m*8+k] matrix m = layer*2+wire; k: 0=ar 1=ai 2=-ai 3=br 4=-br 5=bi 6=-bi 7=-ar
__device__ float2 gStage[89];
__constant__ float2 cC[89];

__global__ void setup_kernel(const float* __restrict__ w1, const float* __restrict__ b1,
                             const float* __restrict__ w2, const float* __restrict__ b2,
                             const float* __restrict__ qw,
                             const float* __restrict__ pw, const float* __restrict__ pb) {
    int tid = threadIdx.x;
    if (tid < 25) {
        float v;
        if (tid < 8)       v = w1[tid];
        else if (tid < 12) v = b1[tid - 8];
        else if (tid < 20) v = w2[tid - 12];
        else if (tid < 22) v = b2[tid - 20];
        else if (tid < 24) v = pw[tid - 22];
        else               v = pb[0];
        gStage[tid] = make_float2(v, v);
    }
    if (tid >= 32 && tid < 40) {
        int m = tid - 32;
        const float* q = qw + m * 3;
        float phi = q[0], th = q[1], om = q[2];
        float st, ct, sp, cp, sm, cm;
        sincosf(0.5f * th, &st, &ct);
        sincosf(0.5f * (phi + om), &sp, &cp);
        sincosf(0.5f * (phi - om), &sm, &cm);
        float ar =  cp * ct, ai = -sp * ct;   // r00 = ep * c
        float br = -cm * st, bi = -sm * st;   // r01 = -conj(em) * s
        float2* R = &gStage[25 + m * 8];
        R[0] = make_float2(ar, ar);
        R[1] = make_float2(ai, ai);
        R[2] = make_float2(-ai, -ai);
        R[3] = make_float2(br, br);
        R[4] = make_float2(-br, -br);
        R[5] = make_float2(bi, bi);
        R[6] = make_float2(-bi, -bi);
        R[7] = make_float2(-ar, -ar);
    }
}

__device__ __forceinline__ p2 ldc(int i) {
    float2 t = cC[i];
    return mk2(t.x, t.y);
}

// SU(2) apply: R = [[A, B], [-conj(B), conj(A)]], pre-negated components given.
__device__ __forceinline__ void apply_rot(p2 ar, p2 ai, p2 nai,
                                          p2 br, p2 nbr, p2 bi, p2 nbi,
                                          p2& ax, p2& ay, p2& bx, p2& by) {
    p2 nax = fma2(nbi, by, fma2(br,  bx, fma2(nai, ay, mul2(ar,  ax))));
    p2 nay = fma2(bi,  bx, fma2(br,  by, fma2(ai,  ax, mul2(ar,  ay))));
    p2 nbx = fma2(ai,  by, fma2(ar,  bx, fma2(nbi, ay, mul2(nbr, ax))));
    p2 nby = fma2(nai, bx, fma2(ar,  by, fma2(bi,  ax, mul2(nbr, ay))));
    ax = nax; ay = nay; bx = nbx; by = nby;
}

// G = R_m * RX(angle): SU(2) with components A=(gar,gai), B=(gbr,gbi)
__device__ __forceinline__ void buildG(int base, p2 c, p2 s,
                                       p2& gar, p2& gai, p2& gbr, p2& gbi) {
    p2 Mar = ldc(base + 0), Mai = ldc(base + 1), Mbr = ldc(base + 3),
       Mnbr = ldc(base + 4), Mbi = ldc(base + 5), Mnar = ldc(base + 7);
    gar = fma2(Mar, c, mul2(Mbi,  s));   // ar*c + bi*s
    gai = fma2(Mai, c, mul2(Mnbr, s));   // ai*c - br*s
    gbr = fma2(Mai, s, mul2(Mbr,  c));   // ai*s + br*c
    gbi = fma2(Mbi, c, mul2(Mnar, s));   // bi*c - ar*s
}

__global__ __launch_bounds__(TPB) void hybrid_qnn_kernel(
    const float4* __restrict__ x4, float4* __restrict__ out4, int B4)
{
    int i = blockIdx.x * TPB + threadIdx.x;
    if (i >= B4) return;

    // ---- 4 samples per thread: 2 independent packed chains ----
    p2 c0[2], s0[2], c1[2], s1[2];
#pragma unroll
    for (int ch = 0; ch < 2; ch++) {
        float4 xv = x4[2 * i + ch];
        p2 X0 = mk2(xv.x, xv.z);
        p2 X1 = mk2(xv.y, xv.w);

        float lo, hi;
        p2 h[4];
#pragma unroll
        for (int j = 0; j < 4; j++) {
            p2 t = fma2(ldc(2*j), X0, fma2(ldc(2*j+1), X1, ldc(8+j)));
            un2(t, lo, hi);
            h[j] = mk2(fast_tanh(lo), fast_tanh(hi));
        }
        p2 t0 = fma2(ldc(12), h[0], fma2(ldc(13), h[1], fma2(ldc(14), h[2], fma2(ldc(15), h[3], ldc(20)))));
        p2 t1 = fma2(ldc(16), h[0], fma2(ldc(17), h[1], fma2(ldc(18), h[2], fma2(ldc(19), h[3], ldc(21)))));

        float a0l, a0h, a1l, a1h;
        un2(t0, a0l, a0h); un2(t1, a1l, a1h);
        a0l = fast_tanh(a0l); a0h = fast_tanh(a0h);
        a1l = fast_tanh(a1l); a1h = fast_tanh(a1h);

        float sl, cl, sh, chh;
        __sincosf(0.5f * a0l, &sl, &cl); __sincosf(0.5f * a0h, &sh, &chh);
        c0[ch] = mk2(cl, chh); s0[ch] = mk2(sl, sh);
        __sincosf(0.5f * a1l, &sl, &cl); __sincosf(0.5f * a1h, &sh, &chh);
        c1[ch] = mk2(cl, chh); s1[ch] = mk2(sl, sh);
    }

    p2 s00x[2], s00y[2], s01x[2], s01y[2], s10x[2], s10y[2], s11x[2], s11y[2];

    // ---- layer 0 on |00>: state = CNOT-perm of (G0 col0) x (G1 col0) ----
#pragma unroll
    for (int ch = 0; ch < 2; ch++) {
        p2 a0r, a0i, b0r, b0i, a1r, a1i, b1r, b1i;
        buildG(25 + 0, c0[ch], s0[ch], a0r, a0i, b0r, b0i);
        buildG(25 + 8, c1[ch], s1[ch], a1r, a1i, b1r, b1i);
        p2 na0r = neg2(a0r), na0i = neg2(a0i), nb0r = neg2(b0r), nb0i = neg2(b0i);
        // pre-CNOT: t00=A0*A1, t01=-A0*conj(B1), t10=-conj(B0)*A1, t11=conj(B0)*conj(B1)
        // post-CNOT labels: s00=t00, s01=t10, s10=t11, s11=t01
        s00x[ch] = fma2(na0i, a1i, mul2(a0r, a1r));
        s00y[ch] = fma2(a0i,  a1r, mul2(a0r, a1i));
        s01x[ch] = fma2(nb0i, a1i, mul2(nb0r, a1r));
        s01y[ch] = fma2(b0i,  a1r, mul2(nb0r, a1i));
        s10x[ch] = fma2(nb0i, b1i, mul2(b0r,  b1r));
        s10y[ch] = fma2(nb0i, b1r, mul2(nb0r, b1i));
        s11x[ch] = fma2(na0i, b1i, mul2(na0r, b1r));
        s11y[ch] = fma2(na0i, b1r, mul2(a0r,  b1i));
    }

    // ---- layers 1..3: fused G = R*RX per wire ----
#pragma unroll
    for (int l = 1; l < NL; l++) {
#pragma unroll
        for (int ch = 0; ch < 2; ch++) {
            {   // wire 0 on pairs (s00,s10), (s01,s11)
                p2 gar, gai, gbr, gbi;
                buildG(25 + (l * 2 + 0) * 8, c0[ch], s0[ch], gar, gai, gbr, gbi);
                p2 ngai = neg2(gai), ngbr = neg2(gbr), ngbi = neg2(gbi);
                apply_rot(gar, gai, ngai, gbr, ngbr, gbi, ngbi,
                          s00x[ch], s00y[ch], s10x[ch], s10y[ch]);
                apply_rot(gar, gai, ngai, gbr, ngbr, gbi, ngbi,
                          s01x[ch], s01y[ch], s11x[ch], s11y[ch]);
            }
            {   // wire 1 on pairs (s00,s01), (s10,s11)
                p2 gar, gai, gbr, gbi;
                buildG(25 + (l * 2 + 1) * 8, c1[ch], s1[ch], gar, gai, gbr, gbi);
                p2 ngai = neg2(gai), ngbr = neg2(gbr), ngbi = neg2(gbi);
                apply_rot(gar, gai, ngai, gbr, ngbr, gbi, ngbi,
                          s00x[ch], s00y[ch], s01x[ch], s01y[ch]);
                apply_rot(gar, gai, ngai, gbr, ngbr, gbi, ngbi,
                          s10x[ch], s10y[ch], s11x[ch], s11y[ch]);
            }
            // CNOT(0,1): swap s10 <-> s11 ; CNOT(1,0): swap s01 <-> s11
            p2 tx = s10x[ch], ty = s10y[ch];
            s10x[ch] = s11x[ch]; s10y[ch] = s11y[ch]; s11x[ch] = tx; s11y[ch] = ty;
            tx = s01x[ch]; ty = s01y[ch];
            s01x[ch] = s11x[ch]; s01y[ch] = s11y[ch]; s11x[ch] = tx; s11y[ch] = ty;
        }
    }

    // ---- measurement; unitarity => q0 = p00+p01, q1 = p00+p10 ----
    float o[4];
#pragma unroll
    for (int ch = 0; ch < 2; ch++) {
        p2 m00 = fma2(s00y[ch], s00y[ch], mul2(s00x[ch], s00x[ch]));
        p2 q0 = fma2(s01y[ch], s01y[ch], fma2(s01x[ch], s01x[ch], m00));
        p2 q1 = fma2(s10y[ch], s10y[ch], fma2(s10x[ch], s10x[ch], m00));
        p2 y = fma2(ldc(22), q0, fma2(ldc(23), q1, ldc(24)));
        float yl, yh;
        un2(y, yl, yh);
        // sigmoid(y) = 0.5*tanh(y/2) + 0.5
        o[2*ch]   = fmaf(0.5f, fast_tanh(0.5f * yl), 0.5f);
        o[2*ch+1] = fmaf(0.5f, fast_tanh(0.5f * yh), 0.5f);
    }
    out4[i] = make_float4(o[0], o[1], o[2], o[3]);
}

extern "C" void kernel_launch(void* const* d_in, const int* in_sizes, int n_in,
                              void* d_out, int out_size) {
    const float4* x  = (const float4*)d_in[0];
    const float* w1  = (const float*)d_in[1];
    const float* b1  = (const float*)d_in[2];
    const float* w2  = (const float*)d_in[3];
    const float* b2  = (const float*)d_in[4];
    const float* qw  = (const float*)d_in[5];
    const float* pw  = (const float*)d_in[6];
    const float* pb  = (const float*)d_in[7];
    float4* out = (float4*)d_out;

    setup_kernel<<<1, 64>>>(w1, b1, w2, b2, qw, pw, pb);

    void* stage_ptr = nullptr;
    cudaGetSymbolAddress(&stage_ptr, gStage);
    cudaMemcpyToSymbolAsync(cC, stage_ptr, 89 * sizeof(float2), 0,
                            cudaMemcpyDeviceToDevice, 0);

    int B4 = in_sizes[0] / 8;  // four samples per thread
    int grid = (B4 + TPB - 1) / TPB;
    hybrid_qnn_kernel<<<grid, TPB>>>(x, out, B4);
}